// round 6
// baseline (speedup 1.0000x reference)
#include <cuda_runtime.h>
#include <math.h>

#define Bn 4096
#define Kn 3000
#define NB 148
#define NT 256
#define NWARP (NB * 8)
#define NCH 12
#define NTI 12
#define RPC 342           /* rows per chunk: ceil(4096/12) */

#define TINYF 1e-12f
#define TOLF  1e-3f
#define INV_EPS 20.0f     /* 1/0.05 */
#define INV_TEMP 10.0f    /* 1/0.1  */

static __device__ float    g_Q[2][(size_t)Bn * Kn];      // ~98 MB scratch
static __device__ float    g_u[2][2][Bn];                // double-buffered u
static __device__ float    g_r[2][Bn];                   // r = Q v
static __device__ float    g_w1[2][Bn];
static __device__ float    g_alpha[2][Bn];
static __device__ float    g_beta[2][Kn];
static __device__ float    g_tpart[2][2][NCH * Kn];      // col-reduction partials
static __device__ unsigned g_rowerr[2][104];
static __device__ unsigned g_colerr[2][104];
static __device__ float    g_ent[2];
static __device__ float    g_qmax[2];
static __device__ float    g_loss;
static __device__ unsigned g_bar_count;
static __device__ unsigned g_bar_gen;

struct Ptrs { const float* p[8]; };

// ---------------- grid barrier (148 resident blocks) -----------------------
// __threadfence() is gpu-scope on sm_103a -> CCTL.IVALL -> L1D invalidated,
// which gives us cross-block coherence for u / tpart / err reads after sync.
static __device__ __forceinline__ void grid_sync()
{
    __syncthreads();
    if (threadIdx.x == 0) {
        volatile unsigned* vgen = &g_bar_gen;
        unsigned gen = *vgen;
        __threadfence();
        unsigned t = atomicAdd(&g_bar_count, 1u);
        if (t == (unsigned)NB - 1u) {
            g_bar_count = 0u;
            __threadfence();
            *vgen = gen + 1u;
        } else {
            while (*vgen == gen) { }
        }
    }
    __threadfence();
    __syncthreads();
}

// ---------------- init ------------------------------------------------------
__global__ void init_kernel()
{
    if (threadIdx.x == 0) {
        g_loss = 0.f;
        g_ent[0] = g_ent[1] = 0.f;
        g_qmax[0] = g_qmax[1] = 0.f;
        g_bar_count = 0u;
    }
}

// ---------------- prep: Q = exp(S - rowmax), S = logits/EPS -----------------
__global__ __launch_bounds__(NT) void prep_kernel(Ptrs ptrs, const int* pia, const int* pib)
{
    __shared__ float red[NT];
    int b = blockIdx.x & (Bn - 1);
    int s = blockIdx.x >> 12;
    int id = (s == 0) ? *pia : *pib;
    const float* lg = ptrs.p[id] + (size_t)b * Kn;
    int tid = threadIdx.x;

    float mx = -3.4e38f;
    for (int k = tid; k < Kn; k += NT) mx = fmaxf(mx, lg[k] * INV_EPS);
    red[tid] = mx; __syncthreads();
    for (int o = NT / 2; o; o >>= 1) {
        if (tid < o) red[tid] = fmaxf(red[tid], red[tid + o]);
        __syncthreads();
    }
    float m = red[0];
    float* q = g_Q[s] + (size_t)b * Kn;
    for (int k = tid; k < Kn; k += NT) q[k] = expf(lg[k] * INV_EPS - m);
}

// ---------------- persistent Sinkhorn (one slot) ----------------------------
__global__ __launch_bounds__(NT) void sinkhorn_kernel(int slot)
{
    const float TC = (float)(4096.0 / 3000.0);
    __shared__ float sv[Kn];
    __shared__ float sred[NT];
    __shared__ float swr[8];
    __shared__ float sqr[8];

    const int tid = threadIdx.x, bid = blockIdx.x;
    const int lane = tid & 31, wid = tid >> 5;
    const float* Qs = g_Q[slot];

    {   // zero per-iteration err arrays
        int i = bid * NT + tid;
        if (i < 104) { g_rowerr[slot][i] = 0u; g_colerr[slot][i] = 0u; }
    }
    grid_sync();

    int n_final = 100;
    for (int iter = 1; iter <= 101; ++iter) {
        const int par = iter & 1, pprev = par ^ 1;

        // materialize v into smem; col_err of iteration iter-1
        float cmax = 0.f;
        for (int k = tid; k < Kn; k += NT) {
            float v;
            if (iter == 1) v = 1.f;
            else {
                float t = 0.f;
                #pragma unroll
                for (int j = 0; j < NCH; ++j) t += g_tpart[slot][pprev][j * Kn + k];
                v = TC / (t + TINYF);
                cmax = fmaxf(cmax, fabsf(v * t - TC));
            }
            sv[k] = v;
        }
        sred[tid] = cmax;
        __syncthreads();
        if (bid == 0 && tid == 0 && iter >= 2) {
            float m = 0.f;
            for (int i = 0; i < NT; ++i) m = fmaxf(m, sred[i]);
            g_colerr[slot][iter - 1] = __float_as_uint(m);
        }
        __syncthreads();

        // rows: r = Q v ; u = 1/(r+TINY) ; row_err of iteration iter-1
        float remax = 0.f;
        for (int row = bid * 8 + wid; row < Bn; row += NWARP) {
            const float* qr = Qs + (size_t)row * Kn;
            float acc = 0.f;
            int k = lane;
            for (; k + 224 < Kn; k += 256) {
                acc += qr[k] * sv[k] + qr[k + 32] * sv[k + 32]
                     + qr[k + 64] * sv[k + 64] + qr[k + 96] * sv[k + 96]
                     + qr[k + 128] * sv[k + 128] + qr[k + 160] * sv[k + 160]
                     + qr[k + 192] * sv[k + 192] + qr[k + 224] * sv[k + 224];
            }
            for (; k < Kn; k += 32) acc += qr[k] * sv[k];
            #pragma unroll
            for (int o = 16; o; o >>= 1) acc += __shfl_xor_sync(0xffffffffu, acc, o);
            if (lane == 0) {
                g_r[slot][row] = acc;
                g_u[slot][par][row] = 1.f / (acc + TINYF);
                if (iter >= 2)
                    remax = fmaxf(remax, fabsf(g_u[slot][pprev][row] * acc - 1.f));
            }
        }
        if (lane == 0) swr[wid] = remax;
        __syncthreads();
        if (tid == 0 && iter >= 2) {
            float m = swr[0];
            #pragma unroll
            for (int w = 1; w < 8; ++w) m = fmaxf(m, swr[w]);
            if (m > 0.f) atomicMax(&g_rowerr[slot][iter - 1], __float_as_uint(m));
        }
        grid_sync();

        if (iter >= 2) {
            int it = iter - 1;
            float err = fmaxf(__uint_as_float(g_rowerr[slot][it]),
                              __uint_as_float(g_colerr[slot][it]));
            if (it >= 3 && (it >= 100 || err <= TOLF)) { n_final = it; break; }
        }

        // cols: t = u^T Q  (deterministic 12-chunk partials)
        if (bid < NTI * NCH) {
            int tile = bid % NTI, chunk = bid / NTI;
            int k = tile * NT + tid;
            if (k < Kn) {
                const float* up = g_u[slot][par];
                int b0 = chunk * RPC, b1 = min(b0 + RPC, Bn);
                const float* qp = Qs + (size_t)b0 * Kn + k;
                float acc = 0.f;
                int b = b0;
                for (; b + 3 < b1; b += 4) {
                    acc += up[b] * qp[0] + up[b + 1] * qp[(size_t)Kn]
                         + up[b + 2] * qp[2 * (size_t)Kn] + up[b + 3] * qp[3 * (size_t)Kn];
                    qp += 4 * (size_t)Kn;
                }
                for (; b < b1; ++b) { acc += up[b] * qp[0]; qp += Kn; }
                g_tpart[slot][par][chunk * Kn + k] = acc;
            }
        }
        grid_sync();
    }

    const int p = n_final & 1;

    // P0: w1_b = u_b / max(u_b*r_b, TINY)
    for (int b = bid * NT + tid; b < Bn; b += NB * NT) {
        float u = g_u[slot][p][b], r = g_r[slot][b];
        g_w1[slot][b] = u / fmaxf(u * r, TINYF);
    }
    grid_sync();

    // P1: column sums of row-normalized P (partials into the other parity)
    if (bid < NTI * NCH) {
        int tile = bid % NTI, chunk = bid / NTI;
        int k = tile * NT + tid;
        if (k < Kn) {
            const float* wp = g_w1[slot];
            int b0 = chunk * RPC, b1 = min(b0 + RPC, Bn);
            const float* qp = Qs + (size_t)b0 * Kn + k;
            float acc = 0.f;
            int b = b0;
            for (; b + 3 < b1; b += 4) {
                acc += wp[b] * qp[0] + wp[b + 1] * qp[(size_t)Kn]
                     + wp[b + 2] * qp[2 * (size_t)Kn] + wp[b + 3] * qp[3 * (size_t)Kn];
                qp += 4 * (size_t)Kn;
            }
            for (; b < b1; ++b) { acc += wp[b] * qp[0]; qp += Kn; }
            g_tpart[slot][1 - p][chunk * Kn + k] = acc;
        }
    }
    grid_sync();

    // P2: beta_k; then per-row rs2 -> alpha, entropy, row-max
    for (int k = tid; k < Kn; k += NT) {
        float t = 0.f, cssum = 0.f;
        #pragma unroll
        for (int j = 0; j < NCH; ++j) {
            t     += g_tpart[slot][p][j * Kn + k];
            cssum += g_tpart[slot][1 - p][j * Kn + k];
        }
        float v = TC / (t + TINYF);
        float cs = v * cssum;
        float beta = v * (TC / fmaxf(cs, TINYF));
        sv[k] = beta;
        if (bid == 0) g_beta[slot][k] = beta;
    }
    __syncthreads();

    float entacc = 0.f, qsum = 0.f;
    for (int row = bid * 8 + wid; row < Bn; row += NWARP) {
        const float* qr = Qs + (size_t)row * Kn;
        float s2 = 0.f;
        for (int k = lane; k < Kn; k += 32) s2 += qr[k] * sv[k];
        #pragma unroll
        for (int o = 16; o; o >>= 1) s2 += __shfl_xor_sync(0xffffffffu, s2, o);
        float w1 = g_w1[slot][row];
        float rs2 = w1 * s2;
        float alpha = w1 / fmaxf(rs2, TINYF);
        if (lane == 0) g_alpha[slot][row] = alpha;
        float qm = 0.f;
        for (int k = lane; k < Kn; k += 32) {
            float p3 = alpha * qr[k] * sv[k];
            entacc += p3 * logf(p3 + TINYF);
            qm = fmaxf(qm, p3);
        }
        #pragma unroll
        for (int o = 16; o; o >>= 1) qm = fmaxf(qm, __shfl_xor_sync(0xffffffffu, qm, o));
        if (lane == 0) qsum += qm;
    }
    #pragma unroll
    for (int o = 16; o; o >>= 1) entacc += __shfl_xor_sync(0xffffffffu, entacc, o);
    __syncthreads();
    if (lane == 0) { swr[wid] = entacc; sqr[wid] = qsum; }
    __syncthreads();
    if (tid == 0) {
        float e = 0.f, q = 0.f;
        #pragma unroll
        for (int w = 0; w < 8; ++w) { e += swr[w]; q += sqr[w]; }
        atomicAdd(&g_ent[slot], e);
        atomicAdd(&g_qmax[slot], q);
    }
}

// ---------------- loss over all 8 crops -------------------------------------
static __device__ __forceinline__ float block_sum(float v, float* red)
{
    red[threadIdx.x] = v; __syncthreads();
    for (int o = NT / 2; o; o >>= 1) {
        if (threadIdx.x < o) red[threadIdx.x] += red[threadIdx.x + o];
        __syncthreads();
    }
    float r = red[0]; __syncthreads();
    return r;
}

__global__ __launch_bounds__(NT) void loss_kernel(Ptrs ptrs, const int* pia, const int* pib)
{
    __shared__ float pa[Kn];
    __shared__ float pb[Kn];
    __shared__ float red[NT];
    int b = blockIdx.x, tid = threadIdx.x;
    int ia = *pia, ib = *pib;

    float aA = g_alpha[0][b], aB = g_alpha[1][b];
    const float* q0 = g_Q[0] + (size_t)b * Kn;
    const float* q1 = g_Q[1] + (size_t)b * Kn;
    for (int k = tid; k < Kn; k += NT) {
        pa[k] = aA * q0[k] * g_beta[0][k];
        pb[k] = aB * q1[k] * g_beta[1][k];
    }
    __syncthreads();

    float accLoss = 0.f;
    for (int c = 0; c < 8; ++c) {
        const float* lr = ptrs.p[c] + (size_t)b * Kn;
        float mx = -3.4e38f;
        for (int k = tid; k < Kn; k += NT) mx = fmaxf(mx, lr[k]);
        red[tid] = mx; __syncthreads();
        for (int o = NT / 2; o; o >>= 1) {
            if (tid < o) red[tid] = fmaxf(red[tid], red[tid + o]);
            __syncthreads();
        }
        float bm = red[0];
        __syncthreads();

        float se = 0.f, da = 0.f, db = 0.f;
        for (int k = tid; k < Kn; k += NT) {
            float x = lr[k];
            se += expf(INV_TEMP * (x - bm));
            da += pa[k] * x;
            db += pb[k] * x;
        }
        se = block_sum(se, red);
        da = block_sum(da, red);
        db = block_sum(db, red);
        if (tid == 0) {
            float lse = INV_TEMP * bm + logf(se);
            if (c != ia) accLoss += INV_TEMP * da - lse;
            if (c != ib) accLoss += INV_TEMP * db - lse;
        }
        __syncthreads();
    }
    if (tid == 0) atomicAdd(&g_loss, accLoss);
}

// ---------------- finalize --------------------------------------------------
__global__ void finalize_kernel(float* out, int out_size)
{
    if (threadIdx.x == 0) {
        float loss = -g_loss / (14.f * (float)Bn);
        float ent  = -0.5f * (g_ent[0] + g_ent[1]) / (float)Bn;
        float qm   =  0.5f * (g_qmax[0] + g_qmax[1]) / (float)Bn;
        if (out_size > 0) out[0] = loss;
        if (out_size > 1) out[1] = ent;
        if (out_size > 2) out[2] = qm;
    }
}

// ---------------- launcher --------------------------------------------------
extern "C" void kernel_launch(void* const* d_in, const int* in_sizes, int n_in,
                              void* d_out, int out_size)
{
    (void)in_sizes; (void)n_in;
    Ptrs ptrs;
    for (int i = 0; i < 8; ++i) ptrs.p[i] = (const float*)d_in[i];
    const int* ia = (const int*)d_in[8];
    const int* ib = (const int*)d_in[9];

    init_kernel<<<1, 32>>>();
    prep_kernel<<<2 * Bn, NT>>>(ptrs, ia, ib);
    sinkhorn_kernel<<<NB, NT>>>(0);
    sinkhorn_kernel<<<NB, NT>>>(1);
    loss_kernel<<<Bn, NT>>>(ptrs, ia, ib);
    finalize_kernel<<<1, 32>>>((float*)d_out, out_size);
}

// round 9
// speedup vs baseline: 2.4131x; 2.4131x over previous
#include <cuda_runtime.h>
#include <cuda_bf16.h>
#include <math.h>

#define Bn 4096
#define Kn 3000
#define KP 3072            /* padded row stride (bf16 elems)   */
#define NBS 148            /* blocks per slot                  */
#define NB2 296            /* total persistent blocks          */
#define NT 256
#define NCH 24             /* col-pass row chunks              */
#define CTIL 6             /* col-pass k2 tiles (bf162 pairs)  */
#define RPC 171            /* rows per chunk ceil(4096/24)     */

#define TINYF 1e-12f
#define TOLF  1e-3f
#define INV_EPS 20.0f      /* 1/0.05 */
#define INV_TEMP 10.0f     /* 1/0.1  */
#define TC 1.3653333333333333f   /* 4096/3000 */

static __device__ __nv_bfloat16 g_Qh[2][(size_t)Bn * KP];     // ~50 MB, L2-resident
static __device__ float    g_u[2][2][Bn];
static __device__ float    g_r[2][Bn];
static __device__ float    g_w1[2][Bn];
static __device__ float    g_alpha[2][Bn];
static __device__ float    g_beta[2][Kn];
static __device__ float    g_v[2][Kn];
static __device__ float    g_tpart[2][2][NCH * KP];
static __device__ unsigned g_rowerr[2][104];
static __device__ unsigned g_colerr[2][104];
static __device__ float    g_ent[2];
static __device__ float    g_qmax[2];
static __device__ float    g_loss;
static __device__ unsigned g_bar_count;
static __device__ unsigned g_bar_gen;

struct Ptrs { const float* p[8]; };

// ---------------- grid barrier (296 resident blocks) ------------------------
static __device__ __forceinline__ void grid_sync()
{
    __syncthreads();
    if (threadIdx.x == 0) {
        volatile unsigned* vgen = &g_bar_gen;
        unsigned gen = *vgen;
        __threadfence();
        unsigned t = atomicAdd(&g_bar_count, 1u);
        if (t == (unsigned)NB2 - 1u) {
            g_bar_count = 0u;
            __threadfence();
            *vgen = gen + 1u;
        } else {
            while (*vgen == gen) { __nanosleep(20); }
        }
        __threadfence();   // CCTL.IVALL -> drop stale L1 lines for whole SM
    }
    __syncthreads();
}

// ---------------- init ------------------------------------------------------
__global__ void init_kernel()
{
    if (threadIdx.x == 0) {
        g_loss = 0.f;
        g_ent[0] = g_ent[1] = 0.f;
        g_qmax[0] = g_qmax[1] = 0.f;
        g_bar_count = 0u;
    }
}

// ---------------- prep: Qh = bf16(exp(S - rowmax)), padded ------------------
__global__ __launch_bounds__(NT) void prep_kernel(Ptrs ptrs, const int* pia, const int* pib)
{
    __shared__ float red[NT];
    int b = blockIdx.x & (Bn - 1);
    int s = blockIdx.x >> 12;
    int id = (s == 0) ? *pia : *pib;
    const float* lg = ptrs.p[id] + (size_t)b * Kn;
    int tid = threadIdx.x;

    float mx = -3.4e38f;
    for (int k = tid; k < Kn; k += NT) mx = fmaxf(mx, lg[k] * INV_EPS);
    red[tid] = mx; __syncthreads();
    for (int o = NT / 2; o; o >>= 1) {
        if (tid < o) red[tid] = fmaxf(red[tid], red[tid + o]);
        __syncthreads();
    }
    float m = red[0];

    __nv_bfloat162* qh = (__nv_bfloat162*)(g_Qh[s] + (size_t)b * KP);
    for (int k2 = tid; k2 < KP / 2; k2 += NT) {
        int k0 = 2 * k2;
        float f0 = (k0     < Kn) ? __expf(lg[k0]     * INV_EPS - m) : 0.f;
        float f1 = (k0 + 1 < Kn) ? __expf(lg[k0 + 1] * INV_EPS - m) : 0.f;
        qh[k2] = __floats2bfloat162_rn(f0, f1);
    }
}

// ---------------- helpers ---------------------------------------------------
static __device__ __forceinline__ float row_dot(const __nv_bfloat16* qrow,
                                                const float4* s4, int lane)
{
    const uint4* qr = (const uint4*)qrow;
    float acc = 0.f;
    #pragma unroll
    for (int j = 0; j < 12; ++j) {       // full unroll: 12 LDG.128 in flight
        int idx = j * 32 + lane;
        uint4 q = qr[idx];
        float4 sa = s4[idx * 2], sb = s4[idx * 2 + 1];
        float2 f0 = __bfloat1622float2(*reinterpret_cast<__nv_bfloat162*>(&q.x));
        float2 f1 = __bfloat1622float2(*reinterpret_cast<__nv_bfloat162*>(&q.y));
        float2 f2 = __bfloat1622float2(*reinterpret_cast<__nv_bfloat162*>(&q.z));
        float2 f3 = __bfloat1622float2(*reinterpret_cast<__nv_bfloat162*>(&q.w));
        acc += f0.x * sa.x + f0.y * sa.y + f1.x * sa.z + f1.y * sa.w
             + f2.x * sb.x + f2.y * sb.y + f3.x * sb.z + f3.y * sb.w;
    }
    return acc;
}

// col pass: tpart[slot][dstpar][chunk*KP + k] = sum_b scal[b] * Q[b][k]
static __device__ __forceinline__ void col_pass(int slot, int sbid, int tid,
                                                const float* scal, int dstpar, float* su)
{
    if (sbid >= CTIL * NCH) return;
    int tile = sbid % CTIL, chunk = sbid / CTIL;
    int b0 = chunk * RPC;
    int nr = min(RPC, Bn - b0);
    for (int i = tid; i < nr; i += NT) su[i] = scal[b0 + i];
    __syncthreads();
    int k2 = tile * NT + tid;
    if (k2 < Kn / 2) {
        const __nv_bfloat162* qp =
            (const __nv_bfloat162*)g_Qh[slot] + (size_t)b0 * (KP / 2) + k2;
        float a0 = 0.f, a1 = 0.f;
        int b = 0;
        for (; b + 16 <= nr; b += 16) {    // 16 LDG.32 in flight per thread
            #pragma unroll
            for (int j = 0; j < 16; ++j) {
                float2 f = __bfloat1622float2(qp[(size_t)j * (KP / 2)]);
                float u = su[b + j];
                a0 += u * f.x; a1 += u * f.y;
            }
            qp += (size_t)16 * (KP / 2);
        }
        for (; b < nr; ++b) {
            float2 f = __bfloat1622float2(qp[0]);
            a0 += su[b] * f.x; a1 += su[b] * f.y;
            qp += KP / 2;
        }
        g_tpart[slot][dstpar][chunk * KP + 2 * k2]     = a0;
        g_tpart[slot][dstpar][chunk * KP + 2 * k2 + 1] = a1;
    }
}

// ---------------- fused persistent Sinkhorn (both crops) --------------------
__global__ __launch_bounds__(NT, 2) void sinkhorn_fused()
{
    __shared__ float sv[KP];
    __shared__ float sred[NT];     // reused as u-chunk buffer in col passes
    __shared__ float swr[8];
    __shared__ float sqr[8];

    const int tid = threadIdx.x, bid = blockIdx.x;
    const int lane = tid & 31, wid = tid >> 5;
    const int slot = (bid >= NBS) ? 1 : 0;
    const int sbid = bid - slot * NBS;
    const __nv_bfloat16* Qs = g_Qh[slot];

    {   // zero err arrays (each slot's blocks zero their own)
        int i = sbid * NT + tid;
        if (i < 104) { g_rowerr[slot][i] = 0u; g_colerr[slot][i] = 0u; }
    }
    grid_sync();

    bool done0 = false, done1 = false;
    int nfin0 = 100, nfin1 = 100;

    for (int iter = 1; iter <= 101; ++iter) {
        const int par = iter & 1, pprev = par ^ 1;
        const bool act = slot ? !done1 : !done0;

        // ---- v-reduce: 12 blocks/slot combine 24 chunk partials -> g_v
        // ce computed by ALL lanes (0 for padded k); the full-mask shuffle is
        // executed warp-uniformly (R7's partial-warp shuffle deadlocked here).
        if (act && iter >= 2 && sbid < 12) {
            int k = sbid * NT + tid;
            float ce = 0.f;
            if (k < Kn) {
                float t = 0.f;
                #pragma unroll
                for (int j = 0; j < NCH; ++j) t += g_tpart[slot][pprev][j * KP + k];
                float v = TC / (t + TINYF);
                g_v[slot][k] = v;
                ce = fabsf(v * t - TC);
            }
            #pragma unroll
            for (int o = 16; o; o >>= 1)
                ce = fmaxf(ce, __shfl_xor_sync(0xffffffffu, ce, o));
            if (lane == 0 && ce > 0.f)
                atomicMax(&g_colerr[slot][iter - 1], __float_as_uint(ce));
        }
        grid_sync();

        // ---- rows: r = Q v, u = 1/(r+TINY), rowerr(iter-1)
        if (act) {
            for (int k = tid; k < KP; k += NT)
                sv[k] = (k < Kn) ? (iter == 1 ? 1.f : g_v[slot][k]) : 0.f;
            __syncthreads();
            float remax = 0.f;
            const float4* s4 = (const float4*)sv;
            for (int row = sbid * 8 + wid; row < Bn; row += NBS * 8) {
                float acc = row_dot(Qs + (size_t)row * KP, s4, lane);
                #pragma unroll
                for (int o = 16; o; o >>= 1)
                    acc += __shfl_xor_sync(0xffffffffu, acc, o);
                if (lane == 0) {
                    g_r[slot][row] = acc;
                    g_u[slot][par][row] = 1.f / (acc + TINYF);
                    if (iter >= 2)
                        remax = fmaxf(remax, fabsf(g_u[slot][pprev][row] * acc - 1.f));
                }
            }
            if (lane == 0) swr[wid] = remax;
            __syncthreads();
            if (tid == 0 && iter >= 2) {
                float m = swr[0];
                #pragma unroll
                for (int w = 1; w < 8; ++w) m = fmaxf(m, swr[w]);
                if (m > 0.f) atomicMax(&g_rowerr[slot][iter - 1], __float_as_uint(m));
            }
        }
        grid_sync();

        // ---- convergence check: identical global data -> uniform decision
        if (iter >= 2) {
            int it = iter - 1;
            if (!done0) {
                float e = fmaxf(__uint_as_float(g_rowerr[0][it]),
                                __uint_as_float(g_colerr[0][it]));
                if (it >= 3 && (it >= 100 || e <= TOLF)) { done0 = true; nfin0 = it; }
            }
            if (!done1) {
                float e = fmaxf(__uint_as_float(g_rowerr[1][it]),
                                __uint_as_float(g_colerr[1][it]));
                if (it >= 3 && (it >= 100 || e <= TOLF)) { done1 = true; nfin1 = it; }
            }
            if (done0 && done1) break;
        }

        // ---- cols: t = u^T Q  (24 deterministic chunks)
        if (slot ? !done1 : !done0)
            col_pass(slot, sbid, tid, g_u[slot][par], par, sred);
        grid_sync();
    }

    const int nfin = slot ? nfin1 : nfin0;
    const int p = nfin & 1;

    // ---- P0: w1_b = u_b / max(u_b*r_b, TINY)
    if (sbid < 16) {
        int b = sbid * NT + tid;
        if (b < Bn) {
            float u = g_u[slot][p][b], r = g_r[slot][b];
            g_w1[slot][b] = u / fmaxf(u * r, TINYF);
        }
    }
    grid_sync();

    // ---- P1: column sums of row-normalized P -> tpart[slot][1-p]
    col_pass(slot, sbid, tid, g_w1[slot], 1 - p, sred);
    grid_sync();

    // ---- beta
    if (sbid < 12) {
        int k = sbid * NT + tid;
        if (k < Kn) {
            float t = 0.f, cssum = 0.f;
            #pragma unroll
            for (int j = 0; j < NCH; ++j) {
                t     += g_tpart[slot][p][j * KP + k];
                cssum += g_tpart[slot][1 - p][j * KP + k];
            }
            float v = TC / (t + TINYF);
            float cs = v * cssum;
            g_beta[slot][k] = v * (TC / fmaxf(cs, TINYF));
        }
    }
    grid_sync();

    // ---- P2: alpha, entropy, q_max (Q row read twice; 2nd sweep L1-hot)
    for (int k = tid; k < KP; k += NT)
        sv[k] = (k < Kn) ? g_beta[slot][k] : 0.f;
    __syncthreads();

    float entacc = 0.f, qsum = 0.f;
    const float4* s4 = (const float4*)sv;
    for (int row = sbid * 8 + wid; row < Bn; row += NBS * 8) {
        float s2 = row_dot(Qs + (size_t)row * KP, s4, lane);
        #pragma unroll
        for (int o = 16; o; o >>= 1)
            s2 += __shfl_xor_sync(0xffffffffu, s2, o);
        float w1 = g_w1[slot][row];
        float alpha = w1 / fmaxf(w1 * s2, TINYF);
        if (lane == 0) g_alpha[slot][row] = alpha;

        const uint4* qr = (const uint4*)(Qs + (size_t)row * KP);
        float qm = 0.f;
        #pragma unroll 4
        for (int j = 0; j < 12; ++j) {
            int idx = j * 32 + lane;
            uint4 q = qr[idx];
            float4 sa = s4[idx * 2], sb = s4[idx * 2 + 1];
            float2 f0 = __bfloat1622float2(*reinterpret_cast<__nv_bfloat162*>(&q.x));
            float2 f1 = __bfloat1622float2(*reinterpret_cast<__nv_bfloat162*>(&q.y));
            float2 f2 = __bfloat1622float2(*reinterpret_cast<__nv_bfloat162*>(&q.z));
            float2 f3 = __bfloat1622float2(*reinterpret_cast<__nv_bfloat162*>(&q.w));
            float pe[8] = { f0.x * sa.x, f0.y * sa.y, f1.x * sa.z, f1.y * sa.w,
                            f2.x * sb.x, f2.y * sb.y, f3.x * sb.z, f3.y * sb.w };
            #pragma unroll
            for (int e = 0; e < 8; ++e) {
                float p3 = alpha * pe[e];
                entacc += p3 * __logf(p3 + TINYF);
                qm = fmaxf(qm, p3);
            }
        }
        #pragma unroll
        for (int o = 16; o; o >>= 1)
            qm = fmaxf(qm, __shfl_xor_sync(0xffffffffu, qm, o));
        if (lane == 0) qsum += qm;
    }
    #pragma unroll
    for (int o = 16; o; o >>= 1)
        entacc += __shfl_xor_sync(0xffffffffu, entacc, o);
    __syncthreads();
    if (lane == 0) { swr[wid] = entacc; sqr[wid] = qsum; }
    __syncthreads();
    if (tid == 0) {
        float e = 0.f, q = 0.f;
        #pragma unroll
        for (int w = 0; w < 8; ++w) { e += swr[w]; q += sqr[w]; }
        atomicAdd(&g_ent[slot], e);
        atomicAdd(&g_qmax[slot], q);
    }
}

// ---------------- loss over all 8 crops -------------------------------------
static __device__ __forceinline__ float block_sum(float v, float* red)
{
    red[threadIdx.x] = v; __syncthreads();
    for (int o = NT / 2; o; o >>= 1) {
        if (threadIdx.x < o) red[threadIdx.x] += red[threadIdx.x + o];
        __syncthreads();
    }
    float r = red[0]; __syncthreads();
    return r;
}

__global__ __launch_bounds__(NT) void loss_kernel(Ptrs ptrs, const int* pia, const int* pib)
{
    __shared__ float pa[Kn];
    __shared__ float pb[Kn];
    __shared__ float red[NT];
    int b = blockIdx.x, tid = threadIdx.x;
    int ia = *pia, ib = *pib;

    float aA = g_alpha[0][b], aB = g_alpha[1][b];
    const __nv_bfloat162* q0 = (const __nv_bfloat162*)(g_Qh[0] + (size_t)b * KP);
    const __nv_bfloat162* q1 = (const __nv_bfloat162*)(g_Qh[1] + (size_t)b * KP);
    for (int k2 = tid; k2 < Kn / 2; k2 += NT) {
        float2 f0 = __bfloat1622float2(q0[k2]);
        float2 f1 = __bfloat1622float2(q1[k2]);
        int k = 2 * k2;
        pa[k]     = aA * f0.x * g_beta[0][k];
        pa[k + 1] = aA * f0.y * g_beta[0][k + 1];
        pb[k]     = aB * f1.x * g_beta[1][k];
        pb[k + 1] = aB * f1.y * g_beta[1][k + 1];
    }
    __syncthreads();

    float accLoss = 0.f;
    for (int c = 0; c < 8; ++c) {
        const float* lr = ptrs.p[c] + (size_t)b * Kn;
        float mx = -3.4e38f;
        for (int k = tid; k < Kn; k += NT) mx = fmaxf(mx, lr[k]);
        red[tid] = mx; __syncthreads();
        for (int o = NT / 2; o; o >>= 1) {
            if (tid < o) red[tid] = fmaxf(red[tid], red[tid + o]);
            __syncthreads();
        }
        float bm = red[0];
        __syncthreads();

        float se = 0.f, da = 0.f, db = 0.f;
        for (int k = tid; k < Kn; k += NT) {
            float x = lr[k];
            se += __expf(INV_TEMP * (x - bm));
            da += pa[k] * x;
            db += pb[k] * x;
        }
        se = block_sum(se, red);
        da = block_sum(da, red);
        db = block_sum(db, red);
        if (tid == 0) {
            float lse = INV_TEMP * bm + logf(se);
            if (c != ia) accLoss += INV_TEMP * da - lse;
            if (c != ib) accLoss += INV_TEMP * db - lse;
        }
        __syncthreads();
    }
    if (tid == 0) atomicAdd(&g_loss, accLoss);
}

// ---------------- finalize --------------------------------------------------
__global__ void finalize_kernel(float* out, int out_size)
{
    if (threadIdx.x == 0) {
        float loss = -g_loss / (14.f * (float)Bn);
        float ent  = -0.5f * (g_ent[0] + g_ent[1]) / (float)Bn;
        float qm   =  0.5f * (g_qmax[0] + g_qmax[1]) / (float)Bn;
        if (out_size > 0) out[0] = loss;
        if (out_size > 1) out[1] = ent;
        if (out_size > 2) out[2] = qm;
    }
}

// ---------------- launcher --------------------------------------------------
extern "C" void kernel_launch(void* const* d_in, const int* in_sizes, int n_in,
                              void* d_out, int out_size)
{
    (void)in_sizes; (void)n_in;
    Ptrs ptrs;
    for (int i = 0; i < 8; ++i) ptrs.p[i] = (const float*)d_in[i];
    const int* ia = (const int*)d_in[8];
    const int* ib = (const int*)d_in[9];

    init_kernel<<<1, 32>>>();
    prep_kernel<<<2 * Bn, NT>>>(ptrs, ia, ib);
    sinkhorn_fused<<<NB2, NT>>>();
    loss_kernel<<<Bn, NT>>>(ptrs, ia, ib);
    finalize_kernel<<<1, 32>>>((float*)d_out, out_size);
}